// round 9
// baseline (speedup 1.0000x reference)
#include <cuda_runtime.h>
#include <cuda_fp16.h>
#include <cstdint>

#define BB 16
#define NN 2048
#define MM 2048
#define DD 128

// ---------------- scratch (__device__ globals: allocation-free rule) --------
__device__ __align__(16) float g_Qsq[BB * NN];
__device__ __align__(16) float g_Ksq[BB * MM];
__device__ __align__(16) uint8_t g_Q8[(size_t)BB * NN * DD];    // e4m3 [b,n,d]
__device__ __align__(16) uint8_t g_KT8[(size_t)BB * MM * DD];   // e4m3 [b,m,d]

// ---------------- helpers ---------------------------------------------------
__device__ __forceinline__ uint32_t smem_u32(const void* p) {
    uint32_t a;
    asm("{ .reg .u64 t; cvta.to.shared.u64 t, %1; cvt.u32.u64 %0, t; }"
        : "=r"(a) : "l"(p));
    return a;
}
__device__ __forceinline__ uint16_t f2_e4m3x2(float hi, float lo) {
    uint16_t r;
    asm("cvt.rn.satfinite.e4m3x2.f32 %0, %1, %2;" : "=h"(r) : "f"(hi), "f"(lo));
    return r;
}
__device__ __forceinline__ void ldsm4(uint32_t* r, uint32_t addr) {
    asm volatile("ldmatrix.sync.aligned.m8n8.x4.shared.b16 {%0,%1,%2,%3}, [%4];"
                 : "=r"(r[0]), "=r"(r[1]), "=r"(r[2]), "=r"(r[3]) : "r"(addr));
}
__device__ __forceinline__ void mma_fp8(float* c, const uint32_t* a,
                                        const uint32_t* b) {
    asm volatile(
        "mma.sync.aligned.m16n8k32.row.col.f32.e4m3.e4m3.f32 "
        "{%0,%1,%2,%3}, {%4,%5,%6,%7}, {%8,%9}, {%0,%1,%2,%3};"
        : "+f"(c[0]), "+f"(c[1]), "+f"(c[2]), "+f"(c[3])
        : "r"(a[0]), "r"(a[1]), "r"(a[2]), "r"(a[3]), "r"(b[0]), "r"(b[1]));
}
__device__ __forceinline__ float ex2a(float x) {
    float y;
    asm("ex2.approx.f32 %0, %1;" : "=f"(y) : "f"(x));
    return y;
}
__device__ __forceinline__ void stcs2(float* p, float x, float y) {
    asm volatile("st.global.cs.v2.f32 [%0], {%1, %2};" :: "l"(p), "f"(x), "f"(y)
                 : "memory");
}

// ---------------------------------------------------------------------------
// Merged prepass. Blocks [0, 4096): Q -> e4m3 + ||q||^2 (one warp per row).
// Blocks [4096, 5120): KV -> transpose to e4m3 [b,m,d] + ||k||^2.
// ---------------------------------------------------------------------------
__global__ void prep(const float* __restrict__ Q, const float* __restrict__ KV) {
    __shared__ float s[128][33];
    __shared__ float csq[256];
    const int t = threadIdx.x;

    if (blockIdx.x < 4096) {
        int row  = blockIdx.x * 8 + (t >> 5);
        int lane = t & 31;
        float4 v = reinterpret_cast<const float4*>(Q + (size_t)row * DD)[lane];
        float sum = v.x * v.x + v.y * v.y + v.z * v.z + v.w * v.w;
        uint32_t pk = (uint32_t)f2_e4m3x2(v.y, v.x)
                    | ((uint32_t)f2_e4m3x2(v.w, v.z) << 16);
        reinterpret_cast<uint32_t*>(g_Q8 + (size_t)row * DD)[lane] = pk;
#pragma unroll
        for (int o = 16; o > 0; o >>= 1) sum += __shfl_xor_sync(0xffffffffu, sum, o);
        if (lane == 0) g_Qsq[row] = sum;
        return;
    }

    const int bid = blockIdx.x - 4096;
    const int b  = bid >> 6;
    const int m0 = (bid & 63) * 32;
    const int mi = t & 31, dg = t >> 5;
    const float* base = KV + (size_t)b * DD * MM + m0;
    float acc = 0.f;
#pragma unroll
    for (int i = 0; i < 16; i++) {
        int d = i * 8 + dg;
        float v = base[(size_t)d * MM + mi];
        s[d][mi] = v;
        acc = fmaf(v, v, acc);
    }
    csq[t] = acc;
    __syncthreads();
    if (t < 32) {
        float a2 = 0.f;
#pragma unroll
        for (int j = 0; j < 8; j++) a2 += csq[t + j * 32];
        g_Ksq[(size_t)b * MM + m0 + t] = a2;
    }
#pragma unroll
    for (int it = 0; it < 2; it++) {
        int idx = it * 256 + t;
        int m = idx >> 4, kc = idx & 15, d0 = kc * 8;
        uint32_t lo = (uint32_t)f2_e4m3x2(s[d0 + 1][m], s[d0 + 0][m])
                    | ((uint32_t)f2_e4m3x2(s[d0 + 3][m], s[d0 + 2][m]) << 16);
        uint32_t hi = (uint32_t)f2_e4m3x2(s[d0 + 5][m], s[d0 + 4][m])
                    | ((uint32_t)f2_e4m3x2(s[d0 + 7][m], s[d0 + 6][m]) << 16);
        *reinterpret_cast<uint2*>(g_KT8 + ((size_t)b * MM + m0 + m) * DD + d0) =
            make_uint2(lo, hi);
    }
}

// ---------------------------------------------------------------------------
// Main kernel: 128(n) x 64(m) tile per CTA, 8 warps in a 4(row)x2(col) grid,
// ldmatrix + mma.sync e4m3, fp32 accumulate, fused exp2 epilogue, .cs stores.
// 3 CTAs/SM (regs capped at 85) for 24 resident warps.
// Smem tiles: 128B pitch; 16B chunks swizzled by (kc ^ (row & 7)).
// ---------------------------------------------------------------------------
#define SM_A 0
#define SM_B 16384
#define SMEM_TOTAL 24576
#define L2E 1.4426950408889634f

__global__ void __launch_bounds__(256, 3)
gauss_mma(const float* __restrict__ LS, float* __restrict__ OUT) {
    extern __shared__ char smem[];
    const uint32_t sb = smem_u32(smem);
    const int t = threadIdx.x, wid = t >> 5, lane = t & 31;
    const int b = blockIdx.z, n0 = blockIdx.y * 128, m0 = blockIdx.x * 64;

    // ---- bulk load operand tiles into swizzled smem ----
    {
        const uint8_t* sA = g_Q8 + ((size_t)b * NN + n0) * DD;   // 128 rows
#pragma unroll
        for (int i = 0; i < 4; i++) {
            int idx = i * 256 + t;
            int row = idx >> 3, kc = idx & 7;
            uint4 v = *reinterpret_cast<const uint4*>(sA + (size_t)row * DD + kc * 16);
            *reinterpret_cast<uint4*>(
                smem + SM_A + row * 128 + ((kc ^ (row & 7)) << 4)) = v;
        }
        const uint8_t* sB = g_KT8 + ((size_t)b * MM + m0) * DD;  // 64 rows
#pragma unroll
        for (int i = 0; i < 2; i++) {
            int idx = i * 256 + t;
            int row = idx >> 3, kc = idx & 7;
            uint4 v = *reinterpret_cast<const uint4*>(sB + (size_t)row * DD + kc * 16);
            *reinterpret_cast<uint4*>(
                smem + SM_B + row * 128 + ((kc ^ (row & 7)) << 4)) = v;
        }
    }
    __syncthreads();

    // ---- fragment addressing ----
    const int warp_r = wid & 3;        // 0..3 -> 32 out-rows each
    const int warp_c = wid >> 2;       // 0..1 -> 32 out-cols each
    const int rmask = lane & 7;

    const int cA = lane >> 4;
    uint32_t arow_base[2];
#pragma unroll
    for (int rt = 0; rt < 2; rt++)
        arow_base[rt] = (uint32_t)((warp_r * 32 + rt * 16 + (lane & 7) +
                                    (((lane >> 3) & 1) << 3)) * 128);
    const int cB = (lane >> 3) & 1;
    uint32_t bcol_base[2];
#pragma unroll
    for (int p = 0; p < 2; p++)
        bcol_base[p] = (uint32_t)((warp_c * 32 + p * 16 + (lane & 7) +
                                   ((lane >> 4) << 3)) * 128);

    float acc[2][4][4];
#pragma unroll
    for (int rt = 0; rt < 2; rt++)
#pragma unroll
        for (int ct = 0; ct < 4; ct++)
#pragma unroll
            for (int j = 0; j < 4; j++) acc[rt][ct][j] = 0.f;

    // ---- main MMA loop: 4 k-steps (k32 each), single e4m3 pass ----
#pragma unroll
    for (int ks = 0; ks < 4; ks++) {
        uint32_t a[2][4], bf[2][4];
        uint32_t aswz = (uint32_t)((((ks << 1) + cA) ^ rmask) << 4);
#pragma unroll
        for (int rt = 0; rt < 2; rt++)
            ldsm4(a[rt], sb + SM_A + arow_base[rt] + aswz);
        uint32_t bswz = (uint32_t)((((ks << 1) + cB) ^ rmask) << 4);
#pragma unroll
        for (int p = 0; p < 2; p++)
            ldsm4(bf[p], sb + SM_B + bcol_base[p] + bswz);

#pragma unroll
        for (int rt = 0; rt < 2; rt++)
#pragma unroll
            for (int ct = 0; ct < 4; ct++)
                mma_fp8(acc[rt][ct], a[rt], bf[ct >> 1] + 2 * (ct & 1));
    }

    // ---- fused Gaussian epilogue (exp2-folded constants) ----
    const float cc   = -0.5f * ex2a(-2.0f * LS[0] * L2E);   // -0.5/exp(2 ls)
    const float ccl  = cc * L2E;
    const float m2cl = -2.0f * ccl;

    const int r_base = n0 + warp_r * 32;
    const int c_base = m0 + warp_c * 32;
    float cq[2][2], ck[4][2];
#pragma unroll
    for (int rt = 0; rt < 2; rt++)
#pragma unroll
        for (int h = 0; h < 2; h++)
            cq[rt][h] = ccl * __ldg(&g_Qsq[(size_t)b * NN + r_base + rt * 16 +
                                           (lane >> 2) + h * 8]);
#pragma unroll
    for (int ct = 0; ct < 4; ct++)
#pragma unroll
        for (int j = 0; j < 2; j++)
            ck[ct][j] = ccl * __ldg(&g_Ksq[(size_t)b * MM + c_base + ct * 8 +
                                           2 * (lane & 3) + j]);

    float* obase = OUT + ((size_t)b * NN + r_base + (lane >> 2)) * MM +
                   c_base + 2 * (lane & 3);
#pragma unroll
    for (int rt = 0; rt < 2; rt++) {
#pragma unroll
        for (int h = 0; h < 2; h++) {
            float* orow = obase + (size_t)(rt * 16 + h * 8) * MM;
#pragma unroll
            for (int ct = 0; ct < 4; ct++) {
                float ox = ex2a(fmaf(m2cl, acc[rt][ct][2 * h + 0],
                                     cq[rt][h] + ck[ct][0]));
                float oy = ex2a(fmaf(m2cl, acc[rt][ct][2 * h + 1],
                                     cq[rt][h] + ck[ct][1]));
                stcs2(orow + ct * 8, ox, oy);
            }
        }
    }
}

// ---------------------------------------------------------------------------
extern "C" void kernel_launch(void* const* d_in, const int* in_sizes, int n_in,
                              void* d_out, int out_size) {
    const float* Q  = (const float*)d_in[0];
    const float* KV = (const float*)d_in[1];
    const float* LS = (const float*)d_in[2];
    float* OUT = (float*)d_out;

    cudaFuncSetAttribute(gauss_mma, cudaFuncAttributeMaxDynamicSharedMemorySize,
                         SMEM_TOTAL);

    prep<<<4096 + 1024, 256>>>(Q, KV);

    dim3 grid(MM / 64, NN / 128, BB);
    gauss_mma<<<grid, 256, SMEM_TOTAL>>>(LS, OUT);
}

// round 10
// speedup vs baseline: 1.0410x; 1.0410x over previous
#include <cuda_runtime.h>
#include <cuda_fp16.h>
#include <cstdint>

#define BB 16
#define NN 2048
#define MM 2048
#define DD 128

// ---------------- scratch (__device__ globals: allocation-free rule) --------
__device__ __align__(16) float g_Qsq[BB * NN];
__device__ __align__(16) float g_Ksq[BB * MM];
__device__ __align__(16) uint8_t g_Q8[(size_t)BB * NN * DD];    // e4m3 [b,n,d]
__device__ __align__(16) uint8_t g_KT8[(size_t)BB * MM * DD];   // e4m3 [b,m,d]

// ---------------- helpers ---------------------------------------------------
__device__ __forceinline__ uint32_t smem_u32(const void* p) {
    uint32_t a;
    asm("{ .reg .u64 t; cvta.to.shared.u64 t, %1; cvt.u32.u64 %0, t; }"
        : "=r"(a) : "l"(p));
    return a;
}
__device__ __forceinline__ uint16_t f2_e4m3x2(float hi, float lo) {
    uint16_t r;
    asm("cvt.rn.satfinite.e4m3x2.f32 %0, %1, %2;" : "=h"(r) : "f"(hi), "f"(lo));
    return r;
}
__device__ __forceinline__ void ldsm4(uint32_t* r, uint32_t addr) {
    asm volatile("ldmatrix.sync.aligned.m8n8.x4.shared.b16 {%0,%1,%2,%3}, [%4];"
                 : "=r"(r[0]), "=r"(r[1]), "=r"(r[2]), "=r"(r[3]) : "r"(addr));
}
__device__ __forceinline__ void mma_fp8(float* c, const uint32_t* a,
                                        const uint32_t* b) {
    asm volatile(
        "mma.sync.aligned.m16n8k32.row.col.f32.e4m3.e4m3.f32 "
        "{%0,%1,%2,%3}, {%4,%5,%6,%7}, {%8,%9}, {%0,%1,%2,%3};"
        : "+f"(c[0]), "+f"(c[1]), "+f"(c[2]), "+f"(c[3])
        : "r"(a[0]), "r"(a[1]), "r"(a[2]), "r"(a[3]), "r"(b[0]), "r"(b[1]));
}
__device__ __forceinline__ float ex2a(float x) {
    float y;
    asm("ex2.approx.f32 %0, %1;" : "=f"(y) : "f"(x));
    return y;
}
__device__ __forceinline__ void stcs2(float* p, float x, float y) {
    asm volatile("st.global.cs.v2.f32 [%0], {%1, %2};" :: "l"(p), "f"(x), "f"(y)
                 : "memory");
}
// packed f32x2 ops (sm_103a)
__device__ __forceinline__ unsigned long long pk2(float lo, float hi) {
    unsigned long long d;
    asm("mov.b64 %0, {%1, %2};" : "=l"(d)
        : "r"(__float_as_uint(lo)), "r"(__float_as_uint(hi)));
    return d;
}
__device__ __forceinline__ unsigned long long pk2dup(float v) {
    unsigned long long d;
    asm("mov.b64 %0, {%1, %1};" : "=l"(d) : "r"(__float_as_uint(v)));
    return d;
}
__device__ __forceinline__ void unpk2(float& lo, float& hi, unsigned long long v) {
    uint32_t a, b2;
    asm("mov.b64 {%0, %1}, %2;" : "=r"(a), "=r"(b2) : "l"(v));
    lo = __uint_as_float(a);
    hi = __uint_as_float(b2);
}
#define ADD2(d, a, b) \
    asm("add.rn.f32x2 %0, %1, %2;" : "=l"(d) : "l"(a), "l"(b))
#define MUL2(d, a, b) \
    asm("mul.rn.f32x2 %0, %1, %2;" : "=l"(d) : "l"(a), "l"(b))
#define FMA2(d, a, b, c) \
    asm("fma.rn.f32x2 %0, %1, %2, %3;" : "=l"(d) : "l"(a), "l"(b), "l"(c))

// ---------------------------------------------------------------------------
// Merged prepass. Blocks [0, 4096): Q -> e4m3 + ||q||^2 (one warp per row).
// Blocks [4096, 5120): KV -> transpose to e4m3 [b,m,d] + ||k||^2.
// ---------------------------------------------------------------------------
__global__ void prep(const float* __restrict__ Q, const float* __restrict__ KV) {
    __shared__ float s[128][33];
    __shared__ float csq[256];
    const int t = threadIdx.x;

    if (blockIdx.x < 4096) {
        int row  = blockIdx.x * 8 + (t >> 5);
        int lane = t & 31;
        float4 v = reinterpret_cast<const float4*>(Q + (size_t)row * DD)[lane];
        float sum = v.x * v.x + v.y * v.y + v.z * v.z + v.w * v.w;
        uint32_t pk = (uint32_t)f2_e4m3x2(v.y, v.x)
                    | ((uint32_t)f2_e4m3x2(v.w, v.z) << 16);
        reinterpret_cast<uint32_t*>(g_Q8 + (size_t)row * DD)[lane] = pk;
#pragma unroll
        for (int o = 16; o > 0; o >>= 1) sum += __shfl_xor_sync(0xffffffffu, sum, o);
        if (lane == 0) g_Qsq[row] = sum;
        return;
    }

    const int bid = blockIdx.x - 4096;
    const int b  = bid >> 6;
    const int m0 = (bid & 63) * 32;
    const int mi = t & 31, dg = t >> 5;
    const float* base = KV + (size_t)b * DD * MM + m0;
    float acc = 0.f;
#pragma unroll
    for (int i = 0; i < 16; i++) {
        int d = i * 8 + dg;
        float v = base[(size_t)d * MM + mi];
        s[d][mi] = v;
        acc = fmaf(v, v, acc);
    }
    csq[t] = acc;
    __syncthreads();
    if (t < 32) {
        float a2 = 0.f;
#pragma unroll
        for (int j = 0; j < 8; j++) a2 += csq[t + j * 32];
        g_Ksq[(size_t)b * MM + m0 + t] = a2;
    }
#pragma unroll
    for (int it = 0; it < 2; it++) {
        int idx = it * 256 + t;
        int m = idx >> 4, kc = idx & 15, d0 = kc * 8;
        uint32_t lo = (uint32_t)f2_e4m3x2(s[d0 + 1][m], s[d0 + 0][m])
                    | ((uint32_t)f2_e4m3x2(s[d0 + 3][m], s[d0 + 2][m]) << 16);
        uint32_t hi = (uint32_t)f2_e4m3x2(s[d0 + 5][m], s[d0 + 4][m])
                    | ((uint32_t)f2_e4m3x2(s[d0 + 7][m], s[d0 + 6][m]) << 16);
        *reinterpret_cast<uint2*>(g_KT8 + ((size_t)b * MM + m0 + m) * DD + d0) =
            make_uint2(lo, hi);
    }
}

// ---------------------------------------------------------------------------
// Main kernel: 128(n) x 128(m) tile per CTA (R7 config), ldmatrix + mma.sync
// e4m3 single pass, fp32 accumulate, packed-f32x2 exp2 epilogue, .cs stores.
// Smem tiles: 128 rows x 128B pitch; 16B chunks swizzled by (kc ^ (row & 7)).
// ---------------------------------------------------------------------------
#define SM_A 0
#define SM_B 16384
#define SMEM_TOTAL 32768
#define L2E 1.4426950408889634f

__global__ void __launch_bounds__(256, 2)
gauss_mma(const float* __restrict__ LS, float* __restrict__ OUT) {
    extern __shared__ char smem[];
    const uint32_t sb = smem_u32(smem);
    const int t = threadIdx.x, wid = t >> 5, lane = t & 31;
    const int b = blockIdx.z, n0 = blockIdx.y * 128, m0 = blockIdx.x * 128;

    // ---- bulk load the 2 operand tiles into swizzled smem ----
    {
        const uint8_t* sA = g_Q8 + ((size_t)b * NN + n0) * DD;
#pragma unroll
        for (int i = 0; i < 4; i++) {
            int idx = i * 256 + t;
            int row = idx >> 3, kc = idx & 7;
            uint4 v = *reinterpret_cast<const uint4*>(sA + (size_t)row * DD + kc * 16);
            *reinterpret_cast<uint4*>(
                smem + SM_A + row * 128 + ((kc ^ (row & 7)) << 4)) = v;
        }
        const uint8_t* sB = g_KT8 + ((size_t)b * MM + m0) * DD;
#pragma unroll
        for (int i = 0; i < 4; i++) {
            int idx = i * 256 + t;
            int row = idx >> 3, kc = idx & 7;
            uint4 v = *reinterpret_cast<const uint4*>(sB + (size_t)row * DD + kc * 16);
            *reinterpret_cast<uint4*>(
                smem + SM_B + row * 128 + ((kc ^ (row & 7)) << 4)) = v;
        }
    }
    __syncthreads();

    // ---- fragment addressing ----
    const int warp_r = wid & 1;        // 0..1 -> 64 out-rows each
    const int warp_c = wid >> 1;       // 0..3 -> 32 out-cols each
    const int rmask = lane & 7;

    const int cA = lane >> 4;
    uint32_t arow_base[4];
#pragma unroll
    for (int rt = 0; rt < 4; rt++)
        arow_base[rt] = (uint32_t)((warp_r * 64 + rt * 16 + (lane & 7) +
                                    (((lane >> 3) & 1) << 3)) * 128);
    const int cB = (lane >> 3) & 1;
    uint32_t bcol_base[2];
#pragma unroll
    for (int p = 0; p < 2; p++)
        bcol_base[p] = (uint32_t)((warp_c * 32 + p * 16 + (lane & 7) +
                                   ((lane >> 4) << 3)) * 128);

    float acc[4][4][4];
#pragma unroll
    for (int rt = 0; rt < 4; rt++)
#pragma unroll
        for (int ct = 0; ct < 4; ct++)
#pragma unroll
            for (int j = 0; j < 4; j++) acc[rt][ct][j] = 0.f;

    // ---- main MMA loop: 4 k-steps (k32 each), single e4m3 pass ----
#pragma unroll
    for (int ks = 0; ks < 4; ks++) {
        uint32_t a[4][4], bf[2][4];
        uint32_t aswz = (uint32_t)((((ks << 1) + cA) ^ rmask) << 4);
#pragma unroll
        for (int rt = 0; rt < 4; rt++)
            ldsm4(a[rt], sb + SM_A + arow_base[rt] + aswz);
        uint32_t bswz = (uint32_t)((((ks << 1) + cB) ^ rmask) << 4);
#pragma unroll
        for (int p = 0; p < 2; p++)
            ldsm4(bf[p], sb + SM_B + bcol_base[p] + bswz);

#pragma unroll
        for (int rt = 0; rt < 4; rt++)
#pragma unroll
            for (int ct = 0; ct < 4; ct++)
                mma_fp8(acc[rt][ct], a[rt], bf[ct >> 1] + 2 * (ct & 1));
    }

    // ---- fused Gaussian epilogue: packed f32x2 + exp2-folded constants ----
    const float cc   = -0.5f * ex2a(-2.0f * LS[0] * L2E);   // -0.5/exp(2 ls)
    const float ccl  = cc * L2E;
    const float m2cl = -2.0f * ccl;
    const unsigned long long m2p  = pk2dup(m2cl);
    const unsigned long long cclp = pk2dup(ccl);

    const int r_base = n0 + warp_r * 64;
    const int c_base = m0 + warp_c * 32;

    // ck pairs: consecutive cols (j=0,1) -> one float2 load + one MUL2 each
    unsigned long long ckp[4];
#pragma unroll
    for (int ct = 0; ct < 4; ct++) {
        float2 kv = *reinterpret_cast<const float2*>(
            &g_Ksq[(size_t)b * MM + c_base + ct * 8 + 2 * (lane & 3)]);
        unsigned long long raw = pk2(kv.x, kv.y);
        MUL2(ckp[ct], raw, cclp);
    }
    float cq[4][2];
#pragma unroll
    for (int rt = 0; rt < 4; rt++)
#pragma unroll
        for (int h = 0; h < 2; h++)
            cq[rt][h] = ccl * __ldg(&g_Qsq[(size_t)b * NN + r_base + rt * 16 +
                                           (lane >> 2) + h * 8]);

    float* obase = OUT + ((size_t)b * NN + r_base + (lane >> 2)) * MM +
                   c_base + 2 * (lane & 3);
#pragma unroll
    for (int rt = 0; rt < 4; rt++) {
#pragma unroll
        for (int h = 0; h < 2; h++) {
            unsigned long long qq = pk2dup(cq[rt][h]);
            float* orow = obase + (size_t)(rt * 16 + h * 8) * MM;
#pragma unroll
            for (int ct = 0; ct < 4; ct++) {
                unsigned long long ap = pk2(acc[rt][ct][2 * h + 0],
                                            acc[rt][ct][2 * h + 1]);
                unsigned long long addend, r;
                ADD2(addend, qq, ckp[ct]);
                FMA2(r, m2p, ap, addend);
                float lo, hi;
                unpk2(lo, hi, r);
                stcs2(orow + ct * 8, ex2a(lo), ex2a(hi));
            }
        }
    }
}

// ---------------------------------------------------------------------------
extern "C" void kernel_launch(void* const* d_in, const int* in_sizes, int n_in,
                              void* d_out, int out_size) {
    const float* Q  = (const float*)d_in[0];
    const float* KV = (const float*)d_in[1];
    const float* LS = (const float*)d_in[2];
    float* OUT = (float*)d_out;

    cudaFuncSetAttribute(gauss_mma, cudaFuncAttributeMaxDynamicSharedMemorySize,
                         SMEM_TOTAL);

    prep<<<4096 + 1024, 256>>>(Q, KV);

    dim3 grid(MM / 128, NN / 128, BB);
    gauss_mma<<<grid, 256, SMEM_TOTAL>>>(LS, OUT);
}

// round 11
// speedup vs baseline: 1.0417x; 1.0007x over previous
#include <cuda_runtime.h>
#include <cuda_fp16.h>
#include <cstdint>

#define BB 16
#define NN 2048
#define MM 2048
#define DD 128

// ---------------- scratch (__device__ globals: allocation-free rule) --------
__device__ __align__(16) float g_Qsq[BB * NN];
__device__ __align__(16) float g_Ksq[BB * MM];
__device__ __align__(16) uint8_t g_Q8[(size_t)BB * NN * DD];    // e4m3 [b,n,d]
__device__ __align__(16) uint8_t g_KT8[(size_t)BB * MM * DD];   // e4m3 [b,m,d]

// ---------------- helpers ---------------------------------------------------
__device__ __forceinline__ uint32_t smem_u32(const void* p) {
    uint32_t a;
    asm("{ .reg .u64 t; cvta.to.shared.u64 t, %1; cvt.u32.u64 %0, t; }"
        : "=r"(a) : "l"(p));
    return a;
}
__device__ __forceinline__ uint16_t f2_e4m3x2(float hi, float lo) {
    uint16_t r;
    asm("cvt.rn.satfinite.e4m3x2.f32 %0, %1, %2;" : "=h"(r) : "f"(hi), "f"(lo));
    return r;
}
__device__ __forceinline__ void ldsm4(uint32_t* r, uint32_t addr) {
    asm volatile("ldmatrix.sync.aligned.m8n8.x4.shared.b16 {%0,%1,%2,%3}, [%4];"
                 : "=r"(r[0]), "=r"(r[1]), "=r"(r[2]), "=r"(r[3]) : "r"(addr));
}
__device__ __forceinline__ void mma_fp8(float* c, const uint32_t* a,
                                        const uint32_t* b) {
    asm volatile(
        "mma.sync.aligned.m16n8k32.row.col.f32.e4m3.e4m3.f32 "
        "{%0,%1,%2,%3}, {%4,%5,%6,%7}, {%8,%9}, {%0,%1,%2,%3};"
        : "+f"(c[0]), "+f"(c[1]), "+f"(c[2]), "+f"(c[3])
        : "r"(a[0]), "r"(a[1]), "r"(a[2]), "r"(a[3]), "r"(b[0]), "r"(b[1]));
}
__device__ __forceinline__ float ex2a(float x) {
    float y;
    asm("ex2.approx.f32 %0, %1;" : "=f"(y) : "f"(x));
    return y;
}
__device__ __forceinline__ void stcs2(float* p, float x, float y) {
    asm volatile("st.global.cs.v2.f32 [%0], {%1, %2};" :: "l"(p), "f"(x), "f"(y)
                 : "memory");
}
__device__ __forceinline__ void cpasync16(uint32_t dst, const void* src) {
    asm volatile("cp.async.cg.shared.global [%0], [%1], 16;"
                 :: "r"(dst), "l"(src) : "memory");
}
__device__ __forceinline__ void cp_commit() {
    asm volatile("cp.async.commit_group;" ::: "memory");
}
__device__ __forceinline__ void cp_wait1() {
    asm volatile("cp.async.wait_group 1;" ::: "memory");
}

// ---------------------------------------------------------------------------
// Merged prepass. Blocks [0, 4096): Q -> e4m3 + ||q||^2 (one warp per row).
// Blocks [4096, 5120): KV -> transpose to e4m3 [b,m,d] + ||k||^2.
// ---------------------------------------------------------------------------
__global__ void prep(const float* __restrict__ Q, const float* __restrict__ KV) {
    __shared__ float s[128][33];
    __shared__ float csq[256];
    const int t = threadIdx.x;

    if (blockIdx.x < 4096) {
        int row  = blockIdx.x * 8 + (t >> 5);
        int lane = t & 31;
        float4 v = reinterpret_cast<const float4*>(Q + (size_t)row * DD)[lane];
        float sum = v.x * v.x + v.y * v.y + v.z * v.z + v.w * v.w;
        uint32_t pk = (uint32_t)f2_e4m3x2(v.y, v.x)
                    | ((uint32_t)f2_e4m3x2(v.w, v.z) << 16);
        reinterpret_cast<uint32_t*>(g_Q8 + (size_t)row * DD)[lane] = pk;
#pragma unroll
        for (int o = 16; o > 0; o >>= 1) sum += __shfl_xor_sync(0xffffffffu, sum, o);
        if (lane == 0) g_Qsq[row] = sum;
        return;
    }

    const int bid = blockIdx.x - 4096;
    const int b  = bid >> 6;
    const int m0 = (bid & 63) * 32;
    const int mi = t & 31, dg = t >> 5;
    const float* base = KV + (size_t)b * DD * MM + m0;
    float acc = 0.f;
#pragma unroll
    for (int i = 0; i < 16; i++) {
        int d = i * 8 + dg;
        float v = base[(size_t)d * MM + mi];
        s[d][mi] = v;
        acc = fmaf(v, v, acc);
    }
    csq[t] = acc;
    __syncthreads();
    if (t < 32) {
        float a2 = 0.f;
#pragma unroll
        for (int j = 0; j < 8; j++) a2 += csq[t + j * 32];
        g_Ksq[(size_t)b * MM + m0 + t] = a2;
    }
#pragma unroll
    for (int it = 0; it < 2; it++) {
        int idx = it * 256 + t;
        int m = idx >> 4, kc = idx & 15, d0 = kc * 8;
        uint32_t lo = (uint32_t)f2_e4m3x2(s[d0 + 1][m], s[d0 + 0][m])
                    | ((uint32_t)f2_e4m3x2(s[d0 + 3][m], s[d0 + 2][m]) << 16);
        uint32_t hi = (uint32_t)f2_e4m3x2(s[d0 + 5][m], s[d0 + 4][m])
                    | ((uint32_t)f2_e4m3x2(s[d0 + 7][m], s[d0 + 6][m]) << 16);
        *reinterpret_cast<uint2*>(g_KT8 + ((size_t)b * MM + m0 + m) * DD + d0) =
            make_uint2(lo, hi);
    }
}

// ---------------------------------------------------------------------------
// Main kernel: persistent 296 CTAs, each looping over 128x128 tiles with a
// double-buffered cp.async pipeline (next tile's operands prefetched during
// current tile's MMA + epilogue). Math identical to the proven R7 kernel;
// epilogue uses exp2-folded constants + ex2.approx.
// Smem: 2 buffers x (A 16KB + B 16KB); 16B chunks swizzled by (kc ^ (row&7)).
// ---------------------------------------------------------------------------
#define GRID 296
#define NTILES 4096
#define BUFSZ 32768
#define SMEM_TOTAL 65536
#define L2E 1.4426950408889634f

__device__ __forceinline__ void issue_tile_cp(int tile, uint32_t bufb, int t) {
    const int b  = tile >> 8;
    const int n0 = ((tile >> 4) & 15) * 128;
    const int m0 = (tile & 15) * 128;
    const uint8_t* sA = g_Q8 + ((size_t)b * NN + n0) * DD;
    const uint8_t* sB = g_KT8 + ((size_t)b * MM + m0) * DD;
#pragma unroll
    for (int i = 0; i < 4; i++) {
        int idx = i * 256 + t;
        int row = idx >> 3, kc = idx & 7;
        uint32_t dst = bufb + row * 128 + ((kc ^ (row & 7)) << 4);
        cpasync16(dst, sA + (size_t)row * DD + kc * 16);
        cpasync16(dst + 16384, sB + (size_t)row * DD + kc * 16);
    }
}

__global__ void __launch_bounds__(256, 2)
gauss_mma(const float* __restrict__ LS, float* __restrict__ OUT) {
    extern __shared__ char smem[];
    const uint32_t sb = smem_u32(smem);
    const int t = threadIdx.x, wid = t >> 5, lane = t & 31;

    // ---- invariant fragment addressing ----
    const int warp_r = wid & 1;        // 0..1 -> 64 out-rows each
    const int warp_c = wid >> 1;       // 0..3 -> 32 out-cols each
    const int rmask = lane & 7;
    const int cA = lane >> 4;
    uint32_t arow_base[4];
#pragma unroll
    for (int rt = 0; rt < 4; rt++)
        arow_base[rt] = (uint32_t)((warp_r * 64 + rt * 16 + (lane & 7) +
                                    (((lane >> 3) & 1) << 3)) * 128);
    const int cB = (lane >> 3) & 1;
    uint32_t bcol_base[2];
#pragma unroll
    for (int p = 0; p < 2; p++)
        bcol_base[p] = (uint32_t)((warp_c * 32 + p * 16 + (lane & 7) +
                                   ((lane >> 4) << 3)) * 128);

    // ---- epilogue constants (exp2-folded), computed once ----
    const float cc   = -0.5f * ex2a(-2.0f * LS[0] * L2E);   // -0.5/exp(2 ls)
    const float ccl  = cc * L2E;
    const float m2cl = -2.0f * ccl;

    // ---- prologue: prefetch first tile into buffer 0 ----
    int tile = blockIdx.x;
    if (tile < NTILES) issue_tile_cp(tile, sb, t);
    cp_commit();

    int cur = 0;
    for (; tile < NTILES; tile += GRID) {
        // prefetch next tile into the other buffer, then wait for current
        int nt = tile + GRID;
        if (nt < NTILES) issue_tile_cp(nt, sb + (cur ^ 1) * BUFSZ, t);
        cp_commit();
        cp_wait1();
        __syncthreads();

        const uint32_t ab = sb + cur * BUFSZ;
        const uint32_t bb = ab + 16384;

        float acc[4][4][4];
#pragma unroll
        for (int rt = 0; rt < 4; rt++)
#pragma unroll
            for (int ct = 0; ct < 4; ct++)
#pragma unroll
                for (int j = 0; j < 4; j++) acc[rt][ct][j] = 0.f;

        // ---- main MMA loop: 4 k-steps (k32 each), single e4m3 pass ----
#pragma unroll
        for (int ks = 0; ks < 4; ks++) {
            uint32_t a[4][4], bf[2][4];
            uint32_t aswz = (uint32_t)((((ks << 1) + cA) ^ rmask) << 4);
#pragma unroll
            for (int rt = 0; rt < 4; rt++)
                ldsm4(a[rt], ab + arow_base[rt] + aswz);
            uint32_t bswz = (uint32_t)((((ks << 1) + cB) ^ rmask) << 4);
#pragma unroll
            for (int p = 0; p < 2; p++)
                ldsm4(bf[p], bb + bcol_base[p] + bswz);

#pragma unroll
            for (int rt = 0; rt < 4; rt++)
#pragma unroll
                for (int ct = 0; ct < 4; ct++)
                    mma_fp8(acc[rt][ct], a[rt], bf[ct >> 1] + 2 * (ct & 1));
        }

        // ---- fused Gaussian epilogue (R7 scalar structure, exp2 folded) ----
        const int b  = tile >> 8;
        const int n0 = ((tile >> 4) & 15) * 128;
        const int m0 = (tile & 15) * 128;
        const int r_base = n0 + warp_r * 64;
        const int c_base = m0 + warp_c * 32;

        float cq[4][2], ck[4][2];
#pragma unroll
        for (int rt = 0; rt < 4; rt++)
#pragma unroll
            for (int h = 0; h < 2; h++)
                cq[rt][h] = ccl * __ldg(&g_Qsq[(size_t)b * NN + r_base + rt * 16 +
                                               (lane >> 2) + h * 8]);
#pragma unroll
        for (int ct = 0; ct < 4; ct++)
#pragma unroll
            for (int j = 0; j < 2; j++)
                ck[ct][j] = ccl * __ldg(&g_Ksq[(size_t)b * MM + c_base + ct * 8 +
                                               2 * (lane & 3) + j]);

        float* obase = OUT + ((size_t)b * NN + r_base + (lane >> 2)) * MM +
                       c_base + 2 * (lane & 3);
#pragma unroll
        for (int rt = 0; rt < 4; rt++) {
#pragma unroll
            for (int ct = 0; ct < 4; ct++) {
#pragma unroll
                for (int h = 0; h < 2; h++) {
                    float* orow = obase + (size_t)(rt * 16 + h * 8) * MM;
                    float ox = ex2a(fmaf(m2cl, acc[rt][ct][2 * h + 0],
                                         cq[rt][h] + ck[ct][0]));
                    float oy = ex2a(fmaf(m2cl, acc[rt][ct][2 * h + 1],
                                         cq[rt][h] + ck[ct][1]));
                    stcs2(orow + ct * 8, ox, oy);
                }
            }
        }

        // all warps done reading buf[cur] before next iter prefetches into it
        __syncthreads();
        cur ^= 1;
    }
}

// ---------------------------------------------------------------------------
extern "C" void kernel_launch(void* const* d_in, const int* in_sizes, int n_in,
                              void* d_out, int out_size) {
    const float* Q  = (const float*)d_in[0];
    const float* KV = (const float*)d_in[1];
    const float* LS = (const float*)d_in[2];
    float* OUT = (float*)d_out;

    cudaFuncSetAttribute(gauss_mma, cudaFuncAttributeMaxDynamicSharedMemorySize,
                         SMEM_TOTAL);

    prep<<<4096 + 1024, 256>>>(Q, KV);

    gauss_mma<<<GRID, 256, SMEM_TOTAL>>>(LS, OUT);
}

// round 12
// speedup vs baseline: 1.1242x; 1.0792x over previous
#include <cuda_runtime.h>
#include <cuda_fp16.h>
#include <cstdint>

#define BB 16
#define NN 2048
#define MM 2048
#define DD 128

// ---------------- scratch (__device__ globals: allocation-free rule) --------
__device__ __align__(16) float g_Qsq[BB * NN];
__device__ __align__(16) float g_Ksq[BB * MM];
__device__ __align__(16) uint8_t g_Q8[(size_t)BB * NN * DD];    // e4m3 [b,n,d]
__device__ __align__(16) uint8_t g_KT8[(size_t)BB * MM * DD];   // e4m3 [b,m,d]

// ---------------- helpers ---------------------------------------------------
__device__ __forceinline__ uint32_t smem_u32(const void* p) {
    uint32_t a;
    asm("{ .reg .u64 t; cvta.to.shared.u64 t, %1; cvt.u32.u64 %0, t; }"
        : "=r"(a) : "l"(p));
    return a;
}
__device__ __forceinline__ uint16_t f2_e4m3x2(float hi, float lo) {
    uint16_t r;
    asm("cvt.rn.satfinite.e4m3x2.f32 %0, %1, %2;" : "=h"(r) : "f"(hi), "f"(lo));
    return r;
}
__device__ __forceinline__ void ldsm4(uint32_t* r, uint32_t addr) {
    asm volatile("ldmatrix.sync.aligned.m8n8.x4.shared.b16 {%0,%1,%2,%3}, [%4];"
                 : "=r"(r[0]), "=r"(r[1]), "=r"(r[2]), "=r"(r[3]) : "r"(addr));
}
__device__ __forceinline__ void mma_fp8(float* c, const uint32_t* a,
                                        const uint32_t* b) {
    asm volatile(
        "mma.sync.aligned.m16n8k32.row.col.f32.e4m3.e4m3.f32 "
        "{%0,%1,%2,%3}, {%4,%5,%6,%7}, {%8,%9}, {%0,%1,%2,%3};"
        : "+f"(c[0]), "+f"(c[1]), "+f"(c[2]), "+f"(c[3])
        : "r"(a[0]), "r"(a[1]), "r"(a[2]), "r"(a[3]), "r"(b[0]), "r"(b[1]));
}
__device__ __forceinline__ float ex2a(float x) {
    float y;
    asm("ex2.approx.f32 %0, %1;" : "=f"(y) : "f"(x));
    return y;
}
__device__ __forceinline__ void stcs2(float* p, float x, float y) {
    asm volatile("st.global.cs.v2.f32 [%0], {%1, %2};" :: "l"(p), "f"(x), "f"(y)
                 : "memory");
}

// ---------------------------------------------------------------------------
// Merged prepass. Blocks [0, 4096): Q -> e4m3 + ||q||^2 (one warp per row).
// Blocks [4096, 5120): KV -> transpose to e4m3 [b,m,d] + ||k||^2.
// ---------------------------------------------------------------------------
__global__ void prep(const float* __restrict__ Q, const float* __restrict__ KV) {
    __shared__ float s[128][33];
    __shared__ float csq[256];
    const int t = threadIdx.x;

    if (blockIdx.x < 4096) {
        int row  = blockIdx.x * 8 + (t >> 5);
        int lane = t & 31;
        float4 v = reinterpret_cast<const float4*>(Q + (size_t)row * DD)[lane];
        float sum = v.x * v.x + v.y * v.y + v.z * v.z + v.w * v.w;
        uint32_t pk = (uint32_t)f2_e4m3x2(v.y, v.x)
                    | ((uint32_t)f2_e4m3x2(v.w, v.z) << 16);
        reinterpret_cast<uint32_t*>(g_Q8 + (size_t)row * DD)[lane] = pk;
#pragma unroll
        for (int o = 16; o > 0; o >>= 1) sum += __shfl_xor_sync(0xffffffffu, sum, o);
        if (lane == 0) g_Qsq[row] = sum;
        return;
    }

    const int bid = blockIdx.x - 4096;
    const int b  = bid >> 6;
    const int m0 = (bid & 63) * 32;
    const int mi = t & 31, dg = t >> 5;
    const float* base = KV + (size_t)b * DD * MM + m0;
    float acc = 0.f;
#pragma unroll
    for (int i = 0; i < 16; i++) {
        int d = i * 8 + dg;
        float v = base[(size_t)d * MM + mi];
        s[d][mi] = v;
        acc = fmaf(v, v, acc);
    }
    csq[t] = acc;
    __syncthreads();
    if (t < 32) {
        float a2 = 0.f;
#pragma unroll
        for (int j = 0; j < 8; j++) a2 += csq[t + j * 32];
        g_Ksq[(size_t)b * MM + m0 + t] = a2;
    }
#pragma unroll
    for (int it = 0; it < 2; it++) {
        int idx = it * 256 + t;
        int m = idx >> 4, kc = idx & 15, d0 = kc * 8;
        uint32_t lo = (uint32_t)f2_e4m3x2(s[d0 + 1][m], s[d0 + 0][m])
                    | ((uint32_t)f2_e4m3x2(s[d0 + 3][m], s[d0 + 2][m]) << 16);
        uint32_t hi = (uint32_t)f2_e4m3x2(s[d0 + 5][m], s[d0 + 4][m])
                    | ((uint32_t)f2_e4m3x2(s[d0 + 7][m], s[d0 + 6][m]) << 16);
        *reinterpret_cast<uint2*>(g_KT8 + ((size_t)b * MM + m0 + m) * DD + d0) =
            make_uint2(lo, hi);
    }
}

// ---------------------------------------------------------------------------
// Main kernel: exact R7 structure (measured best, 84.1us): 128x128 tile per
// CTA, ldmatrix + mma.sync e4m3 single pass, fp32 accumulate, .cs stores.
// Sole change vs R7: exp2-folded epilogue constants + raw ex2.approx
// (removes 32 FMULs/thread that __expf emitted before each MUFU).
// Smem tiles: 128 rows x 128B pitch; 16B chunks swizzled by (kc ^ (row & 7)).
// ---------------------------------------------------------------------------
#define SM_A 0
#define SM_B 16384
#define SMEM_TOTAL 32768
#define L2E 1.4426950408889634f

__global__ void __launch_bounds__(256, 2)
gauss_mma(const float* __restrict__ LS, float* __restrict__ OUT) {
    extern __shared__ char smem[];
    const uint32_t sb = smem_u32(smem);
    const int t = threadIdx.x, wid = t >> 5, lane = t & 31;
    const int b = blockIdx.z, n0 = blockIdx.y * 128, m0 = blockIdx.x * 128;

    // ---- bulk load the 2 operand tiles into swizzled smem ----
    {
        const uint8_t* sA = g_Q8 + ((size_t)b * NN + n0) * DD;
#pragma unroll
        for (int i = 0; i < 4; i++) {
            int idx = i * 256 + t;
            int row = idx >> 3, kc = idx & 7;
            uint4 v = *reinterpret_cast<const uint4*>(sA + (size_t)row * DD + kc * 16);
            *reinterpret_cast<uint4*>(
                smem + SM_A + row * 128 + ((kc ^ (row & 7)) << 4)) = v;
        }
        const uint8_t* sB = g_KT8 + ((size_t)b * MM + m0) * DD;
#pragma unroll
        for (int i = 0; i < 4; i++) {
            int idx = i * 256 + t;
            int row = idx >> 3, kc = idx & 7;
            uint4 v = *reinterpret_cast<const uint4*>(sB + (size_t)row * DD + kc * 16);
            *reinterpret_cast<uint4*>(
                smem + SM_B + row * 128 + ((kc ^ (row & 7)) << 4)) = v;
        }
    }
    __syncthreads();

    // ---- fragment addressing ----
    const int warp_r = wid & 1;        // 0..1 -> 64 out-rows each
    const int warp_c = wid >> 1;       // 0..3 -> 32 out-cols each
    const int rmask = lane & 7;

    const int cA = lane >> 4;
    uint32_t arow_base[4];
#pragma unroll
    for (int rt = 0; rt < 4; rt++)
        arow_base[rt] = (uint32_t)((warp_r * 64 + rt * 16 + (lane & 7) +
                                    (((lane >> 3) & 1) << 3)) * 128);
    const int cB = (lane >> 3) & 1;
    uint32_t bcol_base[2];
#pragma unroll
    for (int p = 0; p < 2; p++)
        bcol_base[p] = (uint32_t)((warp_c * 32 + p * 16 + (lane & 7) +
                                   ((lane >> 4) << 3)) * 128);

    float acc[4][4][4];
#pragma unroll
    for (int rt = 0; rt < 4; rt++)
#pragma unroll
        for (int ct = 0; ct < 4; ct++)
#pragma unroll
            for (int j = 0; j < 4; j++) acc[rt][ct][j] = 0.f;

    // ---- main MMA loop: 4 k-steps (k32 each), single e4m3 pass ----
#pragma unroll
    for (int ks = 0; ks < 4; ks++) {
        uint32_t a[4][4], bf[2][4];
        uint32_t aswz = (uint32_t)((((ks << 1) + cA) ^ rmask) << 4);
#pragma unroll
        for (int rt = 0; rt < 4; rt++)
            ldsm4(a[rt], sb + SM_A + arow_base[rt] + aswz);
        uint32_t bswz = (uint32_t)((((ks << 1) + cB) ^ rmask) << 4);
#pragma unroll
        for (int p = 0; p < 2; p++)
            ldsm4(bf[p], sb + SM_B + bcol_base[p] + bswz);

#pragma unroll
        for (int rt = 0; rt < 4; rt++)
#pragma unroll
            for (int ct = 0; ct < 4; ct++)
                mma_fp8(acc[rt][ct], a[rt], bf[ct >> 1] + 2 * (ct & 1));
    }

    // ---- fused Gaussian epilogue (exp2-folded constants) ----
    const float cc   = -0.5f * ex2a(-2.0f * LS[0] * L2E);   // -0.5/exp(2 ls)
    const float ccl  = cc * L2E;
    const float m2cl = -2.0f * ccl;

    const int r_base = n0 + warp_r * 64;
    const int c_base = m0 + warp_c * 32;
    float cq[4][2], ck[4][2];
#pragma unroll
    for (int rt = 0; rt < 4; rt++)
#pragma unroll
        for (int h = 0; h < 2; h++)
            cq[rt][h] = ccl * __ldg(&g_Qsq[(size_t)b * NN + r_base + rt * 16 +
                                           (lane >> 2) + h * 8]);
#pragma unroll
    for (int ct = 0; ct < 4; ct++)
#pragma unroll
        for (int j = 0; j < 2; j++)
            ck[ct][j] = ccl * __ldg(&g_Ksq[(size_t)b * MM + c_base + ct * 8 +
                                           2 * (lane & 3) + j]);

#pragma unroll
    for (int rt = 0; rt < 4; rt++) {
#pragma unroll
        for (int ct = 0; ct < 4; ct++) {
#pragma unroll
            for (int h = 0; h < 2; h++) {
                int row = r_base + rt * 16 + (lane >> 2) + h * 8;
                int col = c_base + ct * 8 + 2 * (lane & 3);
                float ox = ex2a(fmaf(m2cl, acc[rt][ct][2 * h + 0],
                                     cq[rt][h] + ck[ct][0]));
                float oy = ex2a(fmaf(m2cl, acc[rt][ct][2 * h + 1],
                                     cq[rt][h] + ck[ct][1]));
                stcs2(OUT + ((size_t)b * NN + row) * MM + col, ox, oy);
            }
        }
    }
}

// ---------------------------------------------------------------------------
extern "C" void kernel_launch(void* const* d_in, const int* in_sizes, int n_in,
                              void* d_out, int out_size) {
    const float* Q  = (const float*)d_in[0];
    const float* KV = (const float*)d_in[1];
    const float* LS = (const float*)d_in[2];
    float* OUT = (float*)d_out;

    cudaFuncSetAttribute(gauss_mma, cudaFuncAttributeMaxDynamicSharedMemorySize,
                         SMEM_TOTAL);

    prep<<<4096 + 1024, 256>>>(Q, KV);

    dim3 grid(MM / 128, NN / 128, BB);
    gauss_mma<<<grid, 256, SMEM_TOTAL>>>(LS, OUT);
}